// round 4
// baseline (speedup 1.0000x reference)
#include <cuda_runtime.h>
#include <cuda_fp16.h>

#define NN 100000
#define EE 1600000
#define GG 1000
#define BN_EPS 1e-5f
#define SCAN_NB 98   // ceil(NN/1024)

// ---------------- device scratch ----------------
__device__ int     g_is64;
__device__ int     g_cnt[NN];
__device__ int     g_fill[NN];
__device__ int     g_rowptr[NN + 1];
__device__ int2    g_cw[EE];
__device__ float   g_dinv[NN];
__device__ float   g_bufA[NN * 64];
__device__ float   g_bufB[NN * 64];
__device__ __half2 g_h16A[NN * 32];
__device__ __half2 g_h16B[NN * 32];
__device__ unsigned long long g_scan_pub[SCAN_NB];
__device__ int     g_startg[GG + 1];
__device__ float   g_pool[GG * 128];
__device__ float   g_W0f[3 * 64];
__device__ float   g_b0f[64];
__device__ float   g_Wf[2][64 * 64];
__device__ float   g_bf[2][64];

__device__ __forceinline__ int ld_idx(const void* p, long i, int is64) {
    if (is64) return (int)((const long long*)p)[i];
    return ((const int*)p)[i];
}

// ---------------- prep: detect dtype, zero counters/flags, fold BN ----------------
__global__ void k_prep(const void* ei,
                       const float* __restrict__ W0, const float* __restrict__ b0,
                       const float* __restrict__ Wh, const float* __restrict__ bh,
                       const float* __restrict__ gam, const float* __restrict__ bet,
                       const float* __restrict__ mea, const float* __restrict__ var) {
    int i = blockIdx.x * blockDim.x + threadIdx.x;
    if (i < NN) g_cnt[i] = 0;
    if (i < SCAN_NB) g_scan_pub[i] = 0ULL;

    if (blockIdx.x == 0) {
        __shared__ int sh_any;
        if (threadIdx.x == 0) sh_any = 0;
        __syncthreads();
        long stride = EE / 256;
        long e = (long)threadIdx.x * stride + 1;
        const int* w = (const int*)ei;
        if (w[2 * e + 1] != 0) sh_any = 1;
        __syncthreads();
        if (threadIdx.x == 0) g_is64 = (sh_any == 0) ? 1 : 0;
    } else if (blockIdx.x == 1) {
        for (int t = threadIdx.x; t < 3 * 64; t += 256) {
            int c = t % 64;
            g_W0f[t] = W0[t] * (gam[c] * rsqrtf(var[c] + BN_EPS));
        }
        for (int t = threadIdx.x; t < 64; t += 256) {
            float sc = gam[t] * rsqrtf(var[t] + BN_EPS);
            g_b0f[t] = (b0[t] - mea[t]) * sc + bet[t];
        }
        for (int l = 0; l < 2; ++l) {
            const float* G = gam + 64 * (l + 1);
            const float* B = bet + 64 * (l + 1);
            const float* M = mea + 64 * (l + 1);
            const float* V = var + 64 * (l + 1);
            for (int t = threadIdx.x; t < 64 * 64; t += 256) {
                int c = t % 64;
                g_Wf[l][t] = Wh[l * 4096 + t] * (G[c] * rsqrtf(V[c] + BN_EPS));
            }
            for (int t = threadIdx.x; t < 64; t += 256) {
                float sc = G[t] * rsqrtf(V[t] + BN_EPS);
                g_bf[l][t] = (bh[l * 64 + t] - M[t]) * sc + B[t];
            }
        }
    }
}

// ---------------- count (4 edges/thread, vectorized) + segment bounds ----------------
#define NB_E4 ((EE / 4 + 255) / 256)     // 1563
#define NB_N  ((NN + 255) / 256)

__global__ void k_count_bounds(const void* ei, const void* batch) {
    int is64 = g_is64;
    if (blockIdx.x < NB_E4) {
        int e = (blockIdx.x * 256 + threadIdx.x) * 4;
        if (e >= EE) return;
        int d0, d1, d2, d3;
        if (is64) {
            const longlong2* p = (const longlong2*)((const long long*)ei + EE + e);
            longlong2 a = p[0], b = p[1];
            d0 = (int)a.x; d1 = (int)a.y; d2 = (int)b.x; d3 = (int)b.y;
        } else {
            int4 a = *(const int4*)((const int*)ei + EE + e);
            d0 = a.x; d1 = a.y; d2 = a.z; d3 = a.w;
        }
        atomicAdd(&g_cnt[d0], 1);
        atomicAdd(&g_cnt[d1], 1);
        atomicAdd(&g_cnt[d2], 1);
        atomicAdd(&g_cnt[d3], 1);
    } else {
        int v = (blockIdx.x - NB_E4) * 256 + threadIdx.x;
        if (v >= NN) return;
        int b = ld_idx(batch, v, is64);
        if (v == 0) {
            for (int g = 0; g <= b; ++g) g_startg[g] = 0;
        } else {
            int pb = ld_idx(batch, v - 1, is64);
            for (int g = pb + 1; g <= b; ++g) g_startg[g] = v;
        }
        if (v == NN - 1) {
            for (int g = b + 1; g <= GG; ++g) g_startg[g] = NN;
        }
    }
}

// ---------------- single-pass scan (decoupled lookback) ----------------
__global__ void k_scan() {
    __shared__ int swarp[32];
    __shared__ int s_prev;
    int t = threadIdx.x, b = blockIdx.x;
    int i = b * 1024 + t;
    int v = (i < NN) ? g_cnt[i] : 0;
    int lane = t & 31, w = t >> 5;

    // warp inclusive scan
    int x = v;
#pragma unroll
    for (int off = 1; off < 32; off <<= 1) {
        int y = __shfl_up_sync(0xffffffffu, x, off);
        if (lane >= off) x += y;
    }
    if (lane == 31) swarp[w] = x;
    __syncthreads();
    if (t < 32) {
        int z = swarp[t];
#pragma unroll
        for (int off = 1; off < 32; off <<= 1) {
            int y = __shfl_up_sync(0xffffffffu, z, off);
            if (t >= off) z += y;
        }
        swarp[t] = z;
    }
    __syncthreads();
    int incl = x + (w > 0 ? swarp[w - 1] : 0);
    int agg = swarp[31];

    if (t == 0) {
        if (b == 0) {
            atomicExch(&g_scan_pub[0], (2ULL << 32) | (unsigned)agg);
            s_prev = 0;
        } else {
            atomicExch(&g_scan_pub[b], (1ULL << 32) | (unsigned)agg);
            int run = 0, j = b - 1;
            while (true) {
                unsigned long long p;
                do { p = atomicAdd(&g_scan_pub[j], 0ULL); } while ((p >> 32) == 0);
                int val = (int)(unsigned)p;
                run += val;
                if ((p >> 32) == 2ULL) break;
                --j;
            }
            atomicExch(&g_scan_pub[b], (2ULL << 32) | (unsigned)(run + agg));
            s_prev = run;
        }
    }
    __syncthreads();
    int ex = s_prev + incl - v;   // exclusive prefix
    if (i < NN) {
        g_rowptr[i] = ex;
        g_fill[i] = ex;
        g_dinv[i] = rsqrtf((float)v + 1.0f);
    }
    if (b == 0 && t == 0) g_rowptr[NN] = EE;
}

// ---------------- fill (4 edges/thread, vectorized loads) ----------------
__global__ void k_fill(const void* ei) {
    int is64 = g_is64;
    int e = (blockIdx.x * 256 + threadIdx.x) * 4;
    if (e >= EE) return;
    int s0, s1, s2, s3, d0, d1, d2, d3;
    if (is64) {
        const longlong2* ps = (const longlong2*)((const long long*)ei + e);
        const longlong2* pd = (const longlong2*)((const long long*)ei + EE + e);
        longlong2 sa = ps[0], sb = ps[1], da = pd[0], db = pd[1];
        s0 = (int)sa.x; s1 = (int)sa.y; s2 = (int)sb.x; s3 = (int)sb.y;
        d0 = (int)da.x; d1 = (int)da.y; d2 = (int)db.x; d3 = (int)db.y;
    } else {
        int4 sa = *(const int4*)((const int*)ei + e);
        int4 da = *(const int4*)((const int*)ei + EE + e);
        s0 = sa.x; s1 = sa.y; s2 = sa.z; s3 = sa.w;
        d0 = da.x; d1 = da.y; d2 = da.z; d3 = da.w;
    }
    float w0 = g_dinv[s0] * g_dinv[d0];
    float w1 = g_dinv[s1] * g_dinv[d1];
    float w2 = g_dinv[s2] * g_dinv[d2];
    float w3 = g_dinv[s3] * g_dinv[d3];
    g_cw[atomicAdd(&g_fill[d0], 1)] = make_int2(s0, __float_as_int(w0));
    g_cw[atomicAdd(&g_fill[d1], 1)] = make_int2(s1, __float_as_int(w1));
    g_cw[atomicAdd(&g_fill[d2], 1)] = make_int2(s2, __float_as_int(w2));
    g_cw[atomicAdd(&g_fill[d3], 1)] = make_int2(s3, __float_as_int(w3));
}

// ---------------- layer 0: agg(x) -> @W0f -> ReLU (4 nodes/warp) ----------------
__global__ void k_layer0(const float* __restrict__ x) {
    int warp = threadIdx.x >> 5, lane = threadIdx.x & 31;
    int base = (blockIdx.x * 8 + warp) * 4;
#pragma unroll 1
    for (int n = 0; n < 4; ++n) {
        int v = base + n;
        if (v >= NN) return;
        int r0 = g_rowptr[v], r1 = g_rowptr[v + 1];
        float a0 = 0.f, a1 = 0.f, a2 = 0.f;
        for (int e = r0 + lane; e < r1; e += 32) {
            int2 cw = __ldg(&g_cw[e]);
            int u = cw.x; float w = __int_as_float(cw.y);
            a0 = fmaf(w, __ldg(&x[u * 3 + 0]), a0);
            a1 = fmaf(w, __ldg(&x[u * 3 + 1]), a1);
            a2 = fmaf(w, __ldg(&x[u * 3 + 2]), a2);
        }
#pragma unroll
        for (int o = 16; o > 0; o >>= 1) {
            a0 += __shfl_xor_sync(0xffffffffu, a0, o);
            a1 += __shfl_xor_sync(0xffffffffu, a1, o);
            a2 += __shfl_xor_sync(0xffffffffu, a2, o);
        }
        float dv = g_dinv[v], sw = dv * dv;
        a0 = fmaf(sw, x[v * 3 + 0], a0);
        a1 = fmaf(sw, x[v * 3 + 1], a1);
        a2 = fmaf(sw, x[v * 3 + 2], a2);
        int c = 2 * lane;
        float o0 = a0 * g_W0f[c]     + a1 * g_W0f[64 + c]     + a2 * g_W0f[128 + c]     + g_b0f[c];
        float o1 = a0 * g_W0f[c + 1] + a1 * g_W0f[64 + c + 1] + a2 * g_W0f[128 + c + 1] + g_b0f[c + 1];
        o0 = fmaxf(o0, 0.f);
        o1 = fmaxf(o1, 0.f);
        ((float2*)g_bufA)[v * 32 + lane] = make_float2(o0, o1);
        g_h16A[v * 32 + lane] = __floats2half2_rn(o0, o1);
    }
}

// ---------------- layers 1,2: fp16 gather (x4) + matmul + ReLU + residual (8 nodes/warp) ----------------
__global__ void k_layer(int sel, int write16, int lidx) {
    __shared__ float2 sW[64 * 32];
    const float2* W2 = (const float2*)g_Wf[lidx];
    for (int i = threadIdx.x; i < 2048; i += 256) sW[i] = W2[i];
    __syncthreads();
    int warp = threadIdx.x >> 5, lane = threadIdx.x & 31;
    int base = (blockIdx.x * 8 + warp) * 8;
    if (base >= NN) return;
    const __half2* hin16 = sel ? g_h16B : g_h16A;
    const float2*  hin32 = (const float2*)(sel ? g_bufB : g_bufA);
    float2*        hout32 = (float2*)(sel ? g_bufA : g_bufB);
    __half2*       hout16 = sel ? g_h16A : g_h16B;
    const float*   b = g_bf[lidx];
    int c = 2 * lane;
    float b0v = b[c], b1v = b[c + 1];

#pragma unroll 1
    for (int n = 0; n < 8; ++n) {
        int v = base + n;
        if (v >= NN) return;
        int r0 = g_rowptr[v], r1 = g_rowptr[v + 1];
        float2 acc = make_float2(0.f, 0.f);
        int e = r0;
        for (; e + 4 <= r1; e += 4) {
            int2 c0 = __ldg(&g_cw[e]);
            int2 c1 = __ldg(&g_cw[e + 1]);
            int2 c2 = __ldg(&g_cw[e + 2]);
            int2 c3 = __ldg(&g_cw[e + 3]);
            float2 m0 = __half22float2(__ldg(&hin16[c0.x * 32 + lane]));
            float2 m1 = __half22float2(__ldg(&hin16[c1.x * 32 + lane]));
            float2 m2 = __half22float2(__ldg(&hin16[c2.x * 32 + lane]));
            float2 m3 = __half22float2(__ldg(&hin16[c3.x * 32 + lane]));
            float w0 = __int_as_float(c0.y), w1 = __int_as_float(c1.y);
            float w2 = __int_as_float(c2.y), w3 = __int_as_float(c3.y);
            acc.x = fmaf(w0, m0.x, acc.x); acc.y = fmaf(w0, m0.y, acc.y);
            acc.x = fmaf(w1, m1.x, acc.x); acc.y = fmaf(w1, m1.y, acc.y);
            acc.x = fmaf(w2, m2.x, acc.x); acc.y = fmaf(w2, m2.y, acc.y);
            acc.x = fmaf(w3, m3.x, acc.x); acc.y = fmaf(w3, m3.y, acc.y);
        }
        for (; e < r1; ++e) {
            int2 c0 = __ldg(&g_cw[e]);
            float2 m0 = __half22float2(__ldg(&hin16[c0.x * 32 + lane]));
            float w0 = __int_as_float(c0.y);
            acc.x = fmaf(w0, m0.x, acc.x); acc.y = fmaf(w0, m0.y, acc.y);
        }
        float dv = g_dinv[v], swt = dv * dv;
        float2 hv = hin32[v * 32 + lane];
        acc.x = fmaf(swt, hv.x, acc.x);
        acc.y = fmaf(swt, hv.y, acc.y);

        float2 o = make_float2(0.f, 0.f);
#pragma unroll
        for (int k = 0; k < 32; ++k) {
            float a  = __shfl_sync(0xffffffffu, acc.x, k);
            float bb = __shfl_sync(0xffffffffu, acc.y, k);
            float2 w0 = sW[(2 * k) * 32 + lane];
            float2 w1 = sW[(2 * k + 1) * 32 + lane];
            o.x = fmaf(a, w0.x, o.x); o.x = fmaf(bb, w1.x, o.x);
            o.y = fmaf(a, w0.y, o.y); o.y = fmaf(bb, w1.y, o.y);
        }
        o.x = fmaxf(o.x + b0v, 0.f) + hv.x;
        o.y = fmaxf(o.y + b1v, 0.f) + hv.y;
        hout32[v * 32 + lane] = o;
        if (write16) hout16[v * 32 + lane] = __floats2half2_rn(o.x, o.y);
    }
}

// ---------------- pooling ----------------
__global__ void k_pool() {
    int warp = threadIdx.x >> 5, lane = threadIdx.x & 31;
    int g = blockIdx.x * 8 + warp;
    if (g >= GG) return;
    int s = g_startg[g], e = g_startg[g + 1];
    const float2* h2 = (const float2*)g_bufA;
    float2 sum = make_float2(0.f, 0.f);
    float2 mx = make_float2(-1e30f, -1e30f);
    for (int v = s; v < e; ++v) {
        float2 t = __ldg(&h2[v * 32 + lane]);
        sum.x += t.x; sum.y += t.y;
        mx.x = fmaxf(mx.x, t.x); mx.y = fmaxf(mx.y, t.y);
    }
    float inv = (e > s) ? 1.0f / (float)(e - s) : 0.f;
    int c = 2 * lane;
    g_pool[g * 128 + c]          = sum.x * inv;
    g_pool[g * 128 + c + 1]      = sum.y * inv;
    g_pool[g * 128 + 64 + c]     = mx.x;
    g_pool[g * 128 + 64 + c + 1] = mx.y;
}

// ---------------- MLP head (8 graphs per block) ----------------
__global__ void k_mlp(const float* __restrict__ fc1W, const float* __restrict__ fc1b,
                      const float* __restrict__ fc2W, const float* __restrict__ fc2b,
                      const float* __restrict__ fcgW, const float* __restrict__ fcgb,
                      const float* __restrict__ fcbW, const float* __restrict__ fcbb,
                      float* __restrict__ out) {
    __shared__ float srow[128];
    __shared__ float s1[128];
    __shared__ float rg[64], rb[64];
    int t = threadIdx.x;
    int g0 = blockIdx.x * 8;
#pragma unroll 1
    for (int gi = 0; gi < 8; ++gi) {
        int g = g0 + gi;
        srow[t] = g_pool[g * 128 + t];
        __syncthreads();
        float acc = fc1b[t];
#pragma unroll 8
        for (int k = 0; k < 128; ++k) acc = fmaf(srow[k], __ldg(&fc1W[k * 128 + t]), acc);
        s1[t] = fmaxf(acc, 0.f);
        __syncthreads();
        if (t < 64) {
            float a = fc2b[t];
#pragma unroll 8
            for (int k = 0; k < 128; ++k) a = fmaf(s1[k], __ldg(&fc2W[k * 64 + t]), a);
            float h2v = fmaxf(a, 0.f);
            rg[t] = h2v * fcgW[t];
            rb[t] = h2v * fcbW[t];
        }
        __syncthreads();
        if (t < 32) {
            float a = rg[t] + rg[t + 32];
            float b = rb[t] + rb[t + 32];
#pragma unroll
            for (int o = 16; o > 0; o >>= 1) {
                a += __shfl_down_sync(0xffffffffu, a, o);
                b += __shfl_down_sync(0xffffffffu, b, o);
            }
            if (t == 0) {
                out[g * 2 + 0] = a + fcgb[0];
                out[g * 2 + 1] = b + fcbb[0];
            }
        }
        __syncthreads();
    }
}

// ---------------- launch ----------------
extern "C" void kernel_launch(void* const* d_in, const int* in_sizes, int n_in,
                              void* d_out, int out_size) {
    const float* x    = (const float*)d_in[0];
    const void*  ei   = d_in[1];
    const void*  bat  = d_in[2];
    const float* W0   = (const float*)d_in[3];
    const float* b0   = (const float*)d_in[4];
    const float* Wh   = (const float*)d_in[5];
    const float* bh   = (const float*)d_in[6];
    const float* gam  = (const float*)d_in[7];
    const float* bet  = (const float*)d_in[8];
    const float* mea  = (const float*)d_in[9];
    const float* var  = (const float*)d_in[10];
    const float* fc1W = (const float*)d_in[11];
    const float* fc1b = (const float*)d_in[12];
    const float* fc2W = (const float*)d_in[13];
    const float* fc2b = (const float*)d_in[14];
    const float* fcgW = (const float*)d_in[15];
    const float* fcgb = (const float*)d_in[16];
    const float* fcbW = (const float*)d_in[17];
    const float* fcbb = (const float*)d_in[18];
    float* out = (float*)d_out;

    const int TB = 256;
    const int NB_L = (NN + 63) / 64;       // 8 warps * 8 nodes = 64 nodes/block
    const int NB_L0 = (NN + 31) / 32;      // 8 warps * 4 nodes = 32 nodes/block

    k_prep<<<NB_N, TB>>>(ei, W0, b0, Wh, bh, gam, bet, mea, var);
    k_count_bounds<<<NB_E4 + NB_N, TB>>>(ei, bat);
    k_scan<<<SCAN_NB, 1024>>>();
    k_fill<<<NB_E4, TB>>>(ei);

    k_layer0<<<NB_L0, TB>>>(x);
    k_layer<<<NB_L, TB>>>(0, 1, 0);   // A -> B
    k_layer<<<NB_L, TB>>>(1, 0, 1);   // B -> A

    k_pool<<<(GG + 7) / 8, TB>>>();
    k_mlp<<<GG / 8, 128>>>(fc1W, fc1b, fc2W, fc2b, fcgW, fcgb, fcbW, fcbb, out);
}